// round 6
// baseline (speedup 1.0000x reference)
#include <cuda_runtime.h>
#include <math.h>

#define BB 64
#define TT 1024
#define CC 512
#define TIE_W 1e-3f            // covers fp32 ulp of |score|<6400 (<=4.88e-4) + lp rounding
#define BLOCKS_PER_BATCH 128   // 8 rows/block * 128 blocks = 1024 rows = one batch

// device scratch (allocation-free per harness rules)
__device__ float2 g_m[BB * TT];    // .x = lp1 (= -L), .y = int bits: cls | (tie?1<<30)
__device__ float4 g_lp4[BB * TT];  // tie rows only: top-4 lp (desc)
__device__ int4   g_c4[BB * TT];   // tie rows only: top-4 classes
__device__ int    g_cnt[BB];       // arrival counters (zero-init; self-resetting)

// order-preserving float -> uint key (and inverse)
__device__ __forceinline__ unsigned fkey(float f) {
    unsigned b = __float_as_uint(f);
    return b ^ ((unsigned)((int)b >> 31) | 0x80000000u);
}
__device__ __forceinline__ float unkey(unsigned k) {
    unsigned b = (k & 0x80000000u) ? (k ^ 0x80000000u) : ~k;
    return __uint_as_float(b);
}

// ---------------------------------------------------------------------------
// Fused kernel: 8192 blocks x 256 threads.
//  Phase A (every block): one warp per (b,t) row of 512 logits.
//  Phase B (last-arriving block per batch): sequential fp32 prefix + collapse.
// ---------------------------------------------------------------------------
__global__ __launch_bounds__(256) void fused_kernel(const float* __restrict__ logits,
                                                    float* __restrict__ out_f,
                                                    int* __restrict__ out_i,
                                                    int mode) {
    int tid  = threadIdx.x;
    int lane = tid & 31;
    int warp = tid >> 5;
    int gwarp = blockIdx.x * 8 + warp;   // row id = b*TT + t
    int b = gwarp >> 10;

    // ================= Phase A: per-row reduce =================
    {
        const float4* row = reinterpret_cast<const float4*>(logits + (size_t)gwarp * CC);
        float x[16];
#pragma unroll
        for (int i = 0; i < 4; i++) {
            float4 v = row[lane + 32 * i];  // coalesced LDG.128 x4
            x[4*i+0] = v.x; x[4*i+1] = v.y; x[4*i+2] = v.z; x[4*i+3] = v.w;
        }

        // ---- row max via fmax tree + redux on monotonic key ----
        float m = x[0];
#pragma unroll
        for (int k = 1; k < 16; k++) m = fmaxf(m, x[k]);
        float M = unkey(__reduce_max_sync(0xffffffffu, fkey(m)));

        // ---- argmax class (min class on exact ties) via redux.min ----
        int cand = 0x7fffffff;
#pragma unroll
        for (int i = 3; i >= 0; i--)
#pragma unroll
            for (int j = 3; j >= 0; j--) {
                if (x[4*i+j] == M) cand = 128*i + 4*lane + j;  // ends at smallest match
            }
        int c1 = (int)__reduce_min_sync(0xffffffffu, (unsigned)cand);

        // ---- compensated fp32 sum of exp(x-M)  [bit-identical L] ----
        float s = 0.0f, c = 0.0f;
#pragma unroll
        for (int k = 0; k < 16; k++) {
            float y = __expf(x[k] - M) - c;
            float t = s + y;
            c = (t - s) - y;
            s = t;
        }
        c = -c;
#pragma unroll
        for (int off = 16; off > 0; off >>= 1) {
            float os = __shfl_xor_sync(0xffffffffu, s, off);
            float oc = __shfl_xor_sync(0xffffffffu, c, off);
            float t = s + os;
            float z = t - s;
            float e = (s - (t - z)) + (os - z);
            c = c + oc + e;
            s = t;
        }
        float L = logf(s) + c / s;

        // ---- tie window count via redux.add ----
        float thr = M - TIE_W;
        int cnt = 0;
#pragma unroll
        for (int k = 0; k < 16; k++) cnt += (x[k] >= thr);
        cnt = (int)__reduce_add_sync(0xffffffffu, (unsigned)cnt);

        if (cnt < 2) {
            if (lane == 0)
                g_m[gwarp] = make_float2(-L, __int_as_float(c1));
        } else {
            // rare tie path: full masked top-4 (shuffle argmax passes)
            unsigned sel = 0u;
            float tv[4]; int tc[4];
#pragma unroll
            for (int k = 0; k < 4; k++) {
                float bv = -3.4e38f; int bc = 0x7fffffff;
#pragma unroll
                for (int i = 0; i < 4; i++)
#pragma unroll
                    for (int j = 0; j < 4; j++) {
                        int slot = i * 4 + j;
                        if (!((sel >> slot) & 1u)) {
                            float xv = x[slot];
                            if (xv > bv) { bv = xv; bc = 128*i + 4*lane + j; }
                        }
                    }
#pragma unroll
                for (int off = 16; off > 0; off >>= 1) {
                    float ov = __shfl_xor_sync(0xffffffffu, bv, off);
                    int   oc = __shfl_xor_sync(0xffffffffu, bc, off);
                    if (ov > bv || (ov == bv && oc < bc)) { bv = ov; bc = oc; }
                }
                tv[k] = bv; tc[k] = bc;
                if (((bc >> 2) & 31) == lane) {
                    int i = bc >> 7, j = bc & 3;
                    sel |= 1u << (i * 4 + j);
                }
            }
            if (lane == 0) {
                float4 lp;
                lp.x = -L;
                lp.y = __fadd_rn(__fadd_rn(tv[1], -M), -L);
                lp.z = __fadd_rn(__fadd_rn(tv[2], -M), -L);
                lp.w = __fadd_rn(__fadd_rn(tv[3], -M), -L);
                g_lp4[gwarp] = lp;
                g_c4[gwarp]  = make_int4(tc[0], tc[1], tc[2], tc[3]);
                g_m[gwarp]   = make_float2(-L, __int_as_float(c1 | (1 << 30)));
            }
        }
    }

    // ================= last-block election =================
    __shared__ int s_last;
    __syncthreads();
    if (tid == 0) {
        __threadfence();                          // publish g_m/g_lp4/g_c4
        int old = atomicAdd(&g_cnt[b], 1);
        s_last = (old == BLOCKS_PER_BATCH - 1);
        if (s_last) g_cnt[b] = 0;                 // self-reset for graph replay
    }
    __syncthreads();
    if (!s_last) return;
    __threadfence();                              // acquire peers' writes

    // ================= Phase B: decode batch b =================
    // s_lp MUST be 16B-aligned: the prefix chain uses LDS.128 on it.
    // (round-5 crash: it landed at offset 4 after s_last -> misaligned trap)
    __shared__ __align__(16) float s_lp[TT];
    __shared__ __align__(16) float s_pref[TT];   // written only at tie positions
    __shared__ int      s_cls[TT];
    __shared__ unsigned s_tiem[TT / 32];
    __shared__ float    s_score;

    // stage + tie-mask build + prefill output row with -1
#pragma unroll
    for (int k = 0; k < TT / 256; k++) {
        int t = tid + 256 * k;
        float2 mrec = g_m[b * TT + t];
        int cls = __float_as_int(mrec.y);
        s_lp[t]  = mrec.x;
        s_cls[t] = cls;
        unsigned tm = __ballot_sync(0xffffffffu, (cls & (1 << 30)) != 0);
        if (lane == 0) s_tiem[8 * k + warp] = tm;
        if (mode == 0) out_f[b * TT + t] = -1.0f;
        else           out_i[b * TT + t] = -1;
    }
    __syncthreads();

    // sequential fp32 prefix chain, loads batched ahead of the FADD chain
    if (tid == 0) {
        float s = 0.0f;
        for (int blk = 0; blk < TT; blk += 32) {
            float v[32];
            const float4* lp4 = reinterpret_cast<const float4*>(s_lp + blk);
#pragma unroll
            for (int q = 0; q < 8; q++) {
                float4 f = lp4[q];
                v[4*q+0] = f.x; v[4*q+1] = f.y; v[4*q+2] = f.z; v[4*q+3] = f.w;
            }
            unsigned tm = s_tiem[blk >> 5];
            if (tm == 0u) {
#pragma unroll
                for (int j = 0; j < 32; j++) s = __fadd_rn(s, v[j]);
            } else {
#pragma unroll
                for (int j = 0; j < 32; j++) {
                    if (tm & (1u << j)) s_pref[blk + j] = s;
                    s = __fadd_rn(s, v[j]);
                }
            }
        }
        s_score = s;
    }
    __syncthreads();

    // tie resolution (parallel; flagged rows rare)
#pragma unroll
    for (int k = 0; k < TT / 256; k++) {
        int t = tid + 256 * k;
        int v = s_cls[t];
        if (v & (1 << 30)) {
            float4 lp = g_lp4[b * TT + t];
            int4   cc = g_c4[b * TT + t];
            float  s  = s_pref[t];
            float  r  = __fadd_rn(s, lp.x);
            int ch = cc.x;
            if (__fadd_rn(s, lp.y) == r && cc.y < ch) ch = cc.y;
            if (__fadd_rn(s, lp.z) == r && cc.z < ch) ch = cc.z;
            if (__fadd_rn(s, lp.w) == r && cc.w < ch) ch = cc.w;
            s_cls[t] = ch;
        }
    }
    __syncthreads();

    // warp 0: ballot CTC collapse over shared classes
    if (tid < 32) {
        int carryCnt  = 0;
        int carryPrev = -1;
        unsigned lmask = (lane == 0) ? 0u : (0xffffffffu >> (32 - lane));
        for (int chunk = 0; chunk < TT / 32; chunk++) {
            int t   = chunk * 32 + lane;
            int cls = s_cls[t];
            bool nb = (cls != 0);

            unsigned nbm   = __ballot_sync(0xffffffffu, nb);
            unsigned below = nbm & lmask;
            int src = 31 - __clz(below);
            int pc  = __shfl_sync(0xffffffffu, cls, src & 31);
            int myPrev = below ? pc : carryPrev;

            bool keep = nb && (cls != myPrev);
            unsigned km = __ballot_sync(0xffffffffu, keep);
            int dst = carryCnt + __popc(km & lmask);
            if (keep) {
                if (mode == 0) out_f[b * TT + dst] = (float)cls;
                else           out_i[b * TT + dst] = cls;
            }
            carryCnt += __popc(km);
            if (nbm) carryPrev = __shfl_sync(0xffffffffu, cls, 31 - __clz(nbm));
        }
        if (lane == 0 && mode == 0) {
            out_f[BB * TT + b]      = (float)carryCnt;  // lengths
            out_f[BB * TT + BB + b] = s_score;          // scores[:,0]
        }
    }
}

extern "C" void kernel_launch(void* const* d_in, const int* in_sizes, int n_in,
                              void* d_out, int out_size) {
    const float* logits = (const float*)d_in[0];
    int mode = (out_size == BB * TT) ? 1 : 0;
    fused_kernel<<<(BB * TT) / 8, 256>>>(logits, (float*)d_out, (int*)d_out, mode);
}

// round 7
// speedup vs baseline: 1.2524x; 1.2524x over previous
#include <cuda_runtime.h>
#include <math.h>

#define BB 64
#define TT 1024
#define CC 512
#define TIE_W 1e-3f   // covers fp32 ulp of |score|<6400 (<=4.88e-4) + lp rounding

// device scratch (allocation-free per harness rules)
__device__ float2 g_m[BB * TT];    // .x = lp1 (= -L), .y = int bits: cls | (tie?1<<30)
__device__ float4 g_lp4[BB * TT];  // tie rows only: top-4 lp (desc)
__device__ int4   g_c4[BB * TT];   // tie rows only: top-4 classes

// order-preserving float -> uint key (and inverse)
__device__ __forceinline__ unsigned fkey(float f) {
    unsigned b = __float_as_uint(f);
    return b ^ ((unsigned)((int)b >> 31) | 0x80000000u);
}
__device__ __forceinline__ float unkey(unsigned k) {
    unsigned b = (k & 0x80000000u) ? (k ^ 0x80000000u) : ~k;
    return __uint_as_float(b);
}

// ---------------------------------------------------------------------------
// Kernel A: one warp per (b,t) row of 512 logits (proven round-6 Phase A).
// ---------------------------------------------------------------------------
__global__ __launch_bounds__(256) void row_kernel(const float* __restrict__ logits) {
    int lane  = threadIdx.x & 31;
    int gwarp = blockIdx.x * 8 + (threadIdx.x >> 5);

    const float4* row = reinterpret_cast<const float4*>(logits + (size_t)gwarp * CC);
    float x[16];
#pragma unroll
    for (int i = 0; i < 4; i++) {
        float4 v = row[lane + 32 * i];  // coalesced LDG.128 x4
        x[4*i+0] = v.x; x[4*i+1] = v.y; x[4*i+2] = v.z; x[4*i+3] = v.w;
    }

    // ---- row max via fmax tree + redux on monotonic key ----
    float m = x[0];
#pragma unroll
    for (int k = 1; k < 16; k++) m = fmaxf(m, x[k]);
    float M = unkey(__reduce_max_sync(0xffffffffu, fkey(m)));

    // ---- argmax class (min class on exact ties) via redux.min ----
    int cand = 0x7fffffff;
#pragma unroll
    for (int i = 3; i >= 0; i--)
#pragma unroll
        for (int j = 3; j >= 0; j--) {
            if (x[4*i+j] == M) cand = 128*i + 4*lane + j;  // ends at smallest match
        }
    int c1 = (int)__reduce_min_sync(0xffffffffu, (unsigned)cand);

    // ---- compensated fp32 sum of exp(x-M)  [bit-identical L to all passes] ----
    float s = 0.0f, c = 0.0f;
#pragma unroll
    for (int k = 0; k < 16; k++) {
        float y = __expf(x[k] - M) - c;
        float t = s + y;
        c = (t - s) - y;
        s = t;
    }
    c = -c;
#pragma unroll
    for (int off = 16; off > 0; off >>= 1) {
        float os = __shfl_xor_sync(0xffffffffu, s, off);
        float oc = __shfl_xor_sync(0xffffffffu, c, off);
        float t = s + os;
        float z = t - s;
        float e = (s - (t - z)) + (os - z);
        c = c + oc + e;
        s = t;
    }
    float L = logf(s) + c / s;

    // ---- tie window count via redux.add ----
    float thr = M - TIE_W;
    int cnt = 0;
#pragma unroll
    for (int k = 0; k < 16; k++) cnt += (x[k] >= thr);
    cnt = (int)__reduce_add_sync(0xffffffffu, (unsigned)cnt);

    if (cnt < 2) {
        if (lane == 0)
            g_m[gwarp] = make_float2(-L, __int_as_float(c1));
        return;
    }

    // rare tie path: full masked top-4 (shuffle argmax passes)
    unsigned sel = 0u;
    float tv[4]; int tc[4];
#pragma unroll
    for (int k = 0; k < 4; k++) {
        float bv = -3.4e38f; int bc = 0x7fffffff;
#pragma unroll
        for (int i = 0; i < 4; i++)
#pragma unroll
            for (int j = 0; j < 4; j++) {
                int slot = i * 4 + j;
                if (!((sel >> slot) & 1u)) {
                    float xv = x[slot];
                    if (xv > bv) { bv = xv; bc = 128*i + 4*lane + j; }
                }
            }
#pragma unroll
        for (int off = 16; off > 0; off >>= 1) {
            float ov = __shfl_xor_sync(0xffffffffu, bv, off);
            int   oc = __shfl_xor_sync(0xffffffffu, bc, off);
            if (ov > bv || (ov == bv && oc < bc)) { bv = ov; bc = oc; }
        }
        tv[k] = bv; tc[k] = bc;
        if (((bc >> 2) & 31) == lane) {
            int i = bc >> 7, j = bc & 3;
            sel |= 1u << (i * 4 + j);
        }
    }
    if (lane == 0) {
        float4 lp;
        lp.x = -L;
        lp.y = __fadd_rn(__fadd_rn(tv[1], -M), -L);
        lp.z = __fadd_rn(__fadd_rn(tv[2], -M), -L);
        lp.w = __fadd_rn(__fadd_rn(tv[3], -M), -L);
        g_lp4[gwarp] = lp;
        g_c4[gwarp]  = make_int4(tc[0], tc[1], tc[2], tc[3]);
        g_m[gwarp]   = make_float2(-L, __int_as_float(c1 | (1 << 30)));
    }
}

// ---------------------------------------------------------------------------
// Kernel B: one block (256 thr) per batch.
//  stage -> thread-0 fp32 prefix chain (register-batched LDS.128) -> parallel
//  tie fixup -> PARALLEL 3-pass CTC collapse:
//    keep(t) depends only on raw classes (prev NON-BLANK, not prev kept), so
//    8 warp-segments compose with a 1-bit boundary correction each.
// ---------------------------------------------------------------------------
__global__ __launch_bounds__(256) void scan_decode_kernel(float* __restrict__ out_f,
                                                          int* __restrict__ out_i,
                                                          int mode) {
    int b    = blockIdx.x;
    int tid  = threadIdx.x;
    int lane = tid & 31;
    int warp = tid >> 5;
    unsigned lmask = (lane == 0) ? 0u : (0xffffffffu >> (32 - lane));

    __shared__ __align__(16) float s_lp[TT];
    __shared__ __align__(16) float s_pref[TT];   // written only at tie positions
    __shared__ int      s_cls[TT];
    __shared__ unsigned s_tiem[TT / 32];
    __shared__ unsigned s_keepm[TT / 32];
    __shared__ int s_segFirst[8], s_segLast[8], s_segCnt[8], s_segBase[8], s_segDrop[8];
    __shared__ float s_score;
    __shared__ int   s_len;

    // stage + tie-mask build + prefill output row with -1
#pragma unroll
    for (int k = 0; k < TT / 256; k++) {
        int t = tid + 256 * k;
        float2 mrec = g_m[b * TT + t];
        int cls = __float_as_int(mrec.y);
        s_lp[t]  = mrec.x;
        s_cls[t] = cls;
        unsigned tm = __ballot_sync(0xffffffffu, (cls & (1 << 30)) != 0);
        if (lane == 0) s_tiem[8 * k + warp] = tm;
        if (mode == 0) out_f[b * TT + t] = -1.0f;
        else           out_i[b * TT + t] = -1;
    }
    __syncthreads();

    // sequential fp32 prefix chain, loads batched ahead of the FADD chain
    if (tid == 0) {
        float s = 0.0f;
        for (int blk = 0; blk < TT; blk += 32) {
            float v[32];
            const float4* lp4 = reinterpret_cast<const float4*>(s_lp + blk);
#pragma unroll
            for (int q = 0; q < 8; q++) {
                float4 f = lp4[q];
                v[4*q+0] = f.x; v[4*q+1] = f.y; v[4*q+2] = f.z; v[4*q+3] = f.w;
            }
            unsigned tm = s_tiem[blk >> 5];
            if (tm == 0u) {
#pragma unroll
                for (int j = 0; j < 32; j++) s = __fadd_rn(s, v[j]);
            } else {
#pragma unroll
                for (int j = 0; j < 32; j++) {
                    if (tm & (1u << j)) s_pref[blk + j] = s;
                    s = __fadd_rn(s, v[j]);
                }
            }
        }
        s_score = s;
    }
    __syncthreads();

    // tie resolution (parallel; flagged rows rare)
#pragma unroll
    for (int k = 0; k < TT / 256; k++) {
        int t = tid + 256 * k;
        int v = s_cls[t];
        if (v & (1 << 30)) {
            float4 lp = g_lp4[b * TT + t];
            int4   cc = g_c4[b * TT + t];
            float  s  = s_pref[t];
            float  r  = __fadd_rn(s, lp.x);
            int ch = cc.x;
            if (__fadd_rn(s, lp.y) == r && cc.y < ch) ch = cc.y;
            if (__fadd_rn(s, lp.z) == r && cc.z < ch) ch = cc.z;
            if (__fadd_rn(s, lp.w) == r && cc.w < ch) ch = cc.w;
            s_cls[t] = ch;
        }
    }
    __syncthreads();

    // ---- pass 1: each warp builds keep masks for its 128-elem segment ----
    {
        int carryPrev = -1;   // segment-local; first NB provisionally kept
        int firstCls  = -1;
        int cnt = 0;
#pragma unroll
        for (int j = 0; j < 4; j++) {
            int t   = 128 * warp + 32 * j + lane;
            int cls = s_cls[t];
            bool nb = (cls != 0);

            unsigned nbm   = __ballot_sync(0xffffffffu, nb);
            unsigned below = nbm & lmask;
            int src = 31 - __clz(below);
            int pc  = __shfl_sync(0xffffffffu, cls, src & 31);
            int myPrev = below ? pc : carryPrev;

            bool keep = nb && (cls != myPrev);
            unsigned km = __ballot_sync(0xffffffffu, keep);
            if (lane == 0) s_keepm[4 * warp + j] = km;
            cnt += __popc(km);
            if (nbm) {
                int last = __shfl_sync(0xffffffffu, cls, 31 - __clz(nbm));
                int frst = __shfl_sync(0xffffffffu, cls, __ffs(nbm) - 1);
                carryPrev = last;
                if (firstCls == -1) firstCls = frst;
            }
        }
        if (lane == 0) {
            s_segFirst[warp] = firstCls;
            s_segLast[warp]  = carryPrev;
            s_segCnt[warp]   = cnt;
        }
    }
    __syncthreads();

    // ---- pass 2: thread 0 composes the 8 segment carries ----
    if (tid == 0) {
        int prev = -1, base = 0;
        for (int w = 0; w < 8; w++) {
            int drop = (s_segFirst[w] != -1 && s_segFirst[w] == prev) ? 1 : 0;
            s_segBase[w] = base;
            s_segDrop[w] = drop;
            base += s_segCnt[w] - drop;
            if (s_segLast[w] != -1) prev = s_segLast[w];
        }
        s_len = base;
    }
    __syncthreads();

    // clear dropped first-keep bit (first keep bit == first non-blank)
    if (lane == 0 && s_segDrop[warp]) {
#pragma unroll
        for (int j = 0; j < 4; j++) {
            unsigned km = s_keepm[4 * warp + j];
            if (km) { s_keepm[4 * warp + j] = km & (km - 1); break; }
        }
    }
    __syncwarp();

    // ---- pass 3: compacted writes ----
    {
        int running = s_segBase[warp];
#pragma unroll
        for (int j = 0; j < 4; j++) {
            int t = 128 * warp + 32 * j + lane;
            unsigned km = s_keepm[4 * warp + j];
            bool keep = (km >> lane) & 1u;
            int dst = running + __popc(km & lmask);
            if (keep) {
                int cls = s_cls[t];
                if (mode == 0) out_f[b * TT + dst] = (float)cls;
                else           out_i[b * TT + dst] = cls;
            }
            running += __popc(km);
        }
    }

    if (tid == 0 && mode == 0) {
        out_f[BB * TT + b]      = (float)s_len;   // lengths
        out_f[BB * TT + BB + b] = s_score;        // scores[:,0]
    }
}

extern "C" void kernel_launch(void* const* d_in, const int* in_sizes, int n_in,
                              void* d_out, int out_size) {
    const float* logits = (const float*)d_in[0];

    row_kernel<<<(BB * TT) / 8, 256>>>(logits);

    int mode = (out_size == BB * TT) ? 1 : 0;
    scan_decode_kernel<<<BB, 256>>>((float*)d_out, (int*)d_out, mode);
}